// round 1
// baseline (speedup 1.0000x reference)
#include <cuda_runtime.h>

// DSQGAttentionV10: 20 fixed-offset gather attention.
// B=8,H=16,N=8192,HD=64, J=20 offsets. fp32 in/out.
//
// Block = (b*H+h, 64-position tile). 128 threads: 2 threads per position,
// each owning 32 of the 64 head-dim columns. K/V windows staged in smem
// (XOR-swizzled, stride 64 floats) -> conflict-free LDS.128.
// Two blocks per SM to overlap global window loads with compute.

#define NPOS   8192
#define HDIM   64
#define NHEAD  16
#define NBH    128      // B*H
#define J      20
#define TT     64       // positions per tile
#define HALO   128      // covers offsets <= 128
#define NEARR  (TT + HALO)      // 192 near-window rows
#define NFAR   3                 // offsets 256,512,1024
#define WROWS  (NEARR + NFAR*TT) // 384
#define THREADS 128

#define SMEM_FLOATS (WROWS*HDIM + TT*J + J*HDIM + 32)
#define SMEM_BYTES  (SMEM_FLOATS * 4)

__device__ __forceinline__ int swz(int row, int c4) { return row * 16 + (c4 ^ (row & 7)); }

__global__ void __launch_bounds__(THREADS, 2)
dsqg_kernel(const float* __restrict__ q, const float* __restrict__ k,
            const float* __restrict__ v, const float* __restrict__ pb,
            const float* __restrict__ se, float* __restrict__ out)
{
    const int d_off[J] = {1,2,3,4,5,6,7,8,9,11,13,15,16,23,32,64,128,256,512,1024};

    extern __shared__ float smem[];
    float*  win  = smem;                       // WROWS*64 (swizzled)
    float*  Sbuf = win + WROWS*HDIM;           // TT*J partial scores / probs
    float*  sse  = Sbuf + TT*J;                // J*64 scale_embed
    float*  spb  = sse + J*HDIM;               // J pos_bias for this head

    float4* win4 = (float4*)win;
    const int tid = threadIdx.x;
    const int p   = tid & (TT-1);     // local position
    const int grp = tid >> 6;         // column half: 0 -> cols 0..31, 1 -> 32..63
    const int cb4 = grp * 8;          // float4 column base
    const int bh  = blockIdx.y;
    const int h   = bh & (NHEAD-1);
    const int t0  = blockIdx.x * TT;
    const int n   = t0 + p;
    const size_t base = (size_t)bh * NPOS * HDIM;

    // scale_embed + pos_bias into smem
    for (int i = tid; i < J*HDIM; i += THREADS) sse[i] = se[i];
    if (tid < J) spb[tid] = pb[tid*NHEAD + h];

    // ---- stage q tile into win rows [0,64), then into registers ----
    {
        const float4* qg = (const float4*)(q + base);
        #pragma unroll 4
        for (int idx = tid; idx < TT*16; idx += THREADS) {
            int r = idx >> 4, c4 = idx & 15;
            win4[swz(r, c4)] = qg[(size_t)(t0 + r)*16 + c4];
        }
    }
    __syncthreads();
    float4 qr[8];
    #pragma unroll
    for (int c = 0; c < 8; c++) qr[c] = win4[swz(p, cb4 + c)];
    __syncthreads();

    // ---- load K window (near halo + 3 far windows), zero-filled OOB ----
    {
        const float4* kg = (const float4*)(k + base);
        #pragma unroll 4
        for (int idx = tid; idx < WROWS*16; idx += THREADS) {
            int r = idx >> 4, c4 = idx & 15;
            int fr = r - NEARR;
            int m;
            if (fr < 0) m = t0 - HALO + r;
            else        m = t0 - (256 << (fr >> 6)) + (fr & 63);
            float4 val = make_float4(0.f, 0.f, 0.f, 0.f);
            if (m >= 0) val = kg[(size_t)m*16 + c4];
            win4[swz(r, c4)] = val;
        }
    }
    __syncthreads();

    // ---- phase 1: partial scores over this thread's 32 columns ----
    float s[J];
    #pragma unroll
    for (int j = 0; j < J; j++) s[j] = 0.f;

    #pragma unroll
    for (int j = 0; j < J; j++) {
        const int d   = d_off[j];
        const int row = (j < 17) ? (p + HALO - d) : (NEARR + (j - 17)*TT + p);
        #pragma unroll
        for (int c = 0; c < 8; c++) {
            float4 kv = win4[swz(row, cb4 + c)];
            s[j] += qr[c].x*kv.x + qr[c].y*kv.y + qr[c].z*kv.z + qr[c].w*kv.w;
        }
    }
    // q . scale_embed[j] (broadcast reads)
    {
        const float4* sse4 = (const float4*)sse;
        #pragma unroll
        for (int j = 0; j < J; j++) {
            #pragma unroll
            for (int c = 0; c < 8; c++) {
                float4 e4 = sse4[j*16 + cb4 + c];
                s[j] += qr[c].x*e4.x + qr[c].y*e4.y + qr[c].z*e4.z + qr[c].w*e4.w;
            }
        }
    }

    // combine halves: grp1 writes partials, grp0 finishes + softmax
    if (grp == 1) {
        #pragma unroll
        for (int j = 0; j < J; j++) Sbuf[p*J + j] = s[j];
    }
    __syncthreads();
    if (grp == 0) {
        #pragma unroll
        for (int j = 0; j < J; j++)
            s[j] = (s[j] + Sbuf[p*J + j]) * 0.125f + spb[j];   // sc = 1/sqrt(64)
        float mx = -3.4e38f;
        #pragma unroll
        for (int j = 0; j < J; j++) if (d_off[j] <= n) mx = fmaxf(mx, s[j]);
        float denom = 0.f;
        #pragma unroll
        for (int j = 0; j < J; j++) {
            float e = (d_off[j] <= n) ? __expf(s[j] - mx) : 0.f;
            s[j] = e; denom += e;
        }
        float inv = (denom > 0.f) ? (1.f / denom) : 0.f;
        #pragma unroll
        for (int j = 0; j < J; j++) Sbuf[p*J + j] = s[j] * inv;
    }
    __syncthreads();

    // ---- load V window into the same buffer ----
    {
        const float4* vg = (const float4*)(v + base);
        #pragma unroll 4
        for (int idx = tid; idx < WROWS*16; idx += THREADS) {
            int r = idx >> 4, c4 = idx & 15;
            int fr = r - NEARR;
            int m;
            if (fr < 0) m = t0 - HALO + r;
            else        m = t0 - (256 << (fr >> 6)) + (fr & 63);
            float4 val = make_float4(0.f, 0.f, 0.f, 0.f);
            if (m >= 0) val = vg[(size_t)m*16 + c4];
            win4[swz(r, c4)] = val;
        }
    }
    __syncthreads();

    // ---- phase 3: weighted gather of v ----
    float pj[J];
    #pragma unroll
    for (int j = 0; j < J; j++) pj[j] = Sbuf[p*J + j];

    float4 o[8];
    #pragma unroll
    for (int c = 0; c < 8; c++) o[c] = make_float4(0.f, 0.f, 0.f, 0.f);

    #pragma unroll
    for (int j = 0; j < J; j++) {
        const int d   = d_off[j];
        const int row = (j < 17) ? (p + HALO - d) : (NEARR + (j - 17)*TT + p);
        const float w = pj[j];
        #pragma unroll
        for (int c = 0; c < 8; c++) {
            float4 vv = win4[swz(row, cb4 + c)];
            o[c].x += w * vv.x; o[c].y += w * vv.y;
            o[c].z += w * vv.z; o[c].w += w * vv.w;
        }
    }
    __syncthreads();

    // stage out tile via smem for coalesced stores
    #pragma unroll
    for (int c = 0; c < 8; c++) win4[swz(p, cb4 + c)] = o[c];
    __syncthreads();
    {
        float4* og = (float4*)(out + base);
        #pragma unroll 4
        for (int idx = tid; idx < TT*16; idx += THREADS) {
            int r = idx >> 4, c4 = idx & 15;
            og[(size_t)(t0 + r)*16 + c4] = win4[swz(r, c4)];
        }
    }
}

extern "C" void kernel_launch(void* const* d_in, const int* in_sizes, int n_in,
                              void* d_out, int out_size)
{
    (void)in_sizes; (void)n_in; (void)out_size;
    const float* q  = (const float*)d_in[0];
    const float* k  = (const float*)d_in[1];
    const float* v  = (const float*)d_in[2];
    const float* pb = (const float*)d_in[3];
    const float* se = (const float*)d_in[4];
    float* out = (float*)d_out;

    cudaFuncSetAttribute(dsqg_kernel, cudaFuncAttributeMaxDynamicSharedMemorySize,
                         SMEM_BYTES);

    dim3 grid(NPOS / TT, NBH);   // x = tile (fast-varying) -> L2 locality per (b,h)
    dsqg_kernel<<<grid, THREADS, SMEM_BYTES>>>(q, k, v, pb, se, out);
}

// round 2
// speedup vs baseline: 1.4153x; 1.4153x over previous
#include <cuda_runtime.h>

// DSQGAttentionV10: 20 fixed-offset gather attention. B=8,H=16,N=8192,HD=64, fp32.
//
// Tile = 128 positions of one (b,h). Head-dim processed in two 32-col passes so
// the staged K/V window (640 rows x 32 cols, padded stride) fits 2 blocks/SM.
// 256 threads: 2 threads/position (grp = column half of the 32-col chunk).
// Padded smem stride (9 x 16B units/row) -> conflict-free LDS.128 and
// immediate-offset addressing in the fully unrolled j-loops.

#define NPOS   8192
#define HDIM   64
#define NHEAD  16
#define NBH    128
#define J      20
#define TT     128
#define HALO   128
#define NEARR  (TT + HALO)        // 256 near rows
#define WROWS  (NEARR + 3*TT)     // 640 (far: d=256,512,1024)
#define UPR    9                  // 16B units per row (8 data + 1 pad)
#define THREADS 256

#define SMEM_FLOATS (WROWS*UPR*4 + TT*J + J*HDIM + 32)
#define SMEM_BYTES  (SMEM_FLOATS * 4)

__device__ __forceinline__ float dot4(float4 a, float4 b) {
    return a.x*b.x + a.y*b.y + a.z*b.z + a.w*b.w;
}

__global__ void __launch_bounds__(THREADS, 2)
dsqg_kernel(const float* __restrict__ q, const float* __restrict__ k,
            const float* __restrict__ v, const float* __restrict__ pb,
            const float* __restrict__ se, float* __restrict__ out)
{
    const int d_off[J] = {1,2,3,4,5,6,7,8,9,11,13,15,16,23,32,64,128,256,512,1024};

    extern __shared__ float sm[];
    float4* win4 = (float4*)sm;                    // WROWS*UPR units
    float*  Sbuf = sm + WROWS*UPR*4;               // TT*J partials / probs
    float*  sse  = Sbuf + TT*J;                    // J*64 scale_embed
    float*  spb  = sse + J*HDIM;                   // J pos_bias for this head
    const float4* sse4 = (const float4*)sse;

    const int tid = threadIdx.x;
    const int p   = tid & (TT-1);       // local position
    const int grp = tid >> 7;           // 16-col half of the 32-col chunk
    const int bh  = blockIdx.y;
    const int h   = bh & (NHEAD-1);
    const int t0  = blockIdx.x * TT;
    const int n   = t0 + p;
    const size_t base = (size_t)bh * NPOS * HDIM;
    const int ub  = p*UPR + grp*4;      // thread's base unit in a row-block

    for (int i = tid; i < J*HDIM; i += THREADS) sse[i] = se[i];
    if (tid < J) spb[tid] = pb[tid*NHEAD + h];

    // ---- stage q (both 32-col chunks) and pull into registers ----
    {
        const float4* qg = (const float4*)(q + base);
        #pragma unroll
        for (int it = 0; it < (TT*16)/THREADS; it++) {
            int idx = it*THREADS + tid;
            int r = idx >> 4, c4 = idx & 15;
            int dr = (c4 < 8) ? r : (TT + r);
            win4[dr*UPR + (c4 & 7)] = qg[(size_t)(t0 + r)*16 + c4];
        }
    }
    __syncthreads();
    float4 qa[4], qb[4];
    #pragma unroll
    for (int c = 0; c < 4; c++) {
        qa[c] = win4[ub + c];
        qb[c] = win4[TT*UPR + ub + c];
    }
    __syncthreads();

    float s[J];
    #pragma unroll
    for (int j = 0; j < J; j++) s[j] = 0.f;

    // ================= K passes (two 32-col chunks) =================
    #pragma unroll
    for (int pass = 0; pass < 2; pass++) {
        {   // stage window chunk
            const float4* gg = (const float4*)(k + base);
            #pragma unroll
            for (int it = 0; it < (WROWS*8)/THREADS; it++) {
                int idx = it*THREADS + tid;
                int r = idx >> 3, c4 = idx & 7;
                int m;
                if (r < NEARR) m = t0 - HALO + r;
                else { int fr = r - NEARR; m = t0 - (256 << (fr >> 7)) + (fr & (TT-1)); }
                float4 val = make_float4(0.f,0.f,0.f,0.f);
                if (m >= 0) val = gg[(size_t)m*16 + pass*8 + c4];
                win4[r*UPR + c4] = val;
            }
        }
        __syncthreads();

        #pragma unroll
        for (int j = 0; j < J; j++) {
            const int d = d_off[j];
            const int rowc = (j < 17) ? (HALO - d) : (NEARR + (j-17)*TT);
            const int ib = rowc*UPR + ub;           // base + p*UPR folded in ub
            #pragma unroll
            for (int c = 0; c < 4; c++) {
                float4 qv = (pass == 0) ? qa[c] : qb[c];
                s[j] += dot4(qv, win4[ib + c]);
                s[j] += dot4(qv, sse4[j*16 + pass*8 + grp*4 + c]);
            }
        }
        __syncthreads();
    }

    // ---- combine halves + softmax (grp0 finishes) ----
    if (grp == 1) {
        #pragma unroll
        for (int j = 0; j < J; j++) Sbuf[p*J + j] = s[j];
    }
    __syncthreads();
    if (grp == 0) {
        #pragma unroll
        for (int j = 0; j < J; j++)
            s[j] = (s[j] + Sbuf[p*J + j]) * 0.125f + spb[j];
        float mx = -3.4e38f;
        #pragma unroll
        for (int j = 0; j < J; j++) if (d_off[j] <= n) mx = fmaxf(mx, s[j]);
        float denom = 0.f;
        #pragma unroll
        for (int j = 0; j < J; j++) {
            float e = (d_off[j] <= n) ? __expf(s[j] - mx) : 0.f;
            s[j] = e; denom += e;
        }
        float inv = (denom > 0.f) ? (1.f / denom) : 0.f;
        #pragma unroll
        for (int j = 0; j < J; j++) Sbuf[p*J + j] = s[j] * inv;
    }
    __syncthreads();

    float pj[J];
    #pragma unroll
    for (int j = 0; j < J; j++) pj[j] = Sbuf[p*J + j];

    // ================= V passes (two 32-col chunks) =================
    #pragma unroll
    for (int pass = 0; pass < 2; pass++) {
        {   // stage window chunk
            const float4* gg = (const float4*)(v + base);
            #pragma unroll
            for (int it = 0; it < (WROWS*8)/THREADS; it++) {
                int idx = it*THREADS + tid;
                int r = idx >> 3, c4 = idx & 7;
                int m;
                if (r < NEARR) m = t0 - HALO + r;
                else { int fr = r - NEARR; m = t0 - (256 << (fr >> 7)) + (fr & (TT-1)); }
                float4 val = make_float4(0.f,0.f,0.f,0.f);
                if (m >= 0) val = gg[(size_t)m*16 + pass*8 + c4];
                win4[r*UPR + c4] = val;
            }
        }
        __syncthreads();

        float4 o[4];
        #pragma unroll
        for (int c = 0; c < 4; c++) o[c] = make_float4(0.f,0.f,0.f,0.f);

        #pragma unroll
        for (int j = 0; j < J; j++) {
            const int d = d_off[j];
            const int rowc = (j < 17) ? (HALO - d) : (NEARR + (j-17)*TT);
            const int ib = rowc*UPR + ub;
            const float w = pj[j];
            #pragma unroll
            for (int c = 0; c < 4; c++) {
                float4 vv = win4[ib + c];
                o[c].x += w*vv.x; o[c].y += w*vv.y;
                o[c].z += w*vv.z; o[c].w += w*vv.w;
            }
        }
        __syncthreads();

        // stage out chunk via smem for coalesced stores
        #pragma unroll
        for (int c = 0; c < 4; c++) win4[ub + c] = o[c];
        __syncthreads();
        {
            float4* og = (float4*)(out + base);
            #pragma unroll
            for (int it = 0; it < (TT*8)/THREADS; it++) {
                int idx = it*THREADS + tid;
                int r = idx >> 3, c4 = idx & 7;
                og[(size_t)(t0 + r)*16 + pass*8 + c4] = win4[r*UPR + c4];
            }
        }
        __syncthreads();
    }
}

extern "C" void kernel_launch(void* const* d_in, const int* in_sizes, int n_in,
                              void* d_out, int out_size)
{
    (void)in_sizes; (void)n_in; (void)out_size;
    const float* q  = (const float*)d_in[0];
    const float* k  = (const float*)d_in[1];
    const float* v  = (const float*)d_in[2];
    const float* pb = (const float*)d_in[3];
    const float* se = (const float*)d_in[4];
    float* out = (float*)d_out;

    cudaFuncSetAttribute(dsqg_kernel, cudaFuncAttributeMaxDynamicSharedMemorySize,
                         SMEM_BYTES);

    dim3 grid(NPOS / TT, NBH);
    dsqg_kernel<<<grid, THREADS, SMEM_BYTES>>>(q, k, v, pb, se, out);
}